// round 1
// baseline (speedup 1.0000x reference)
#include <cuda_runtime.h>
#include <cuda_fp16.h>
#include <cstdint>

// Problem constants
#define BB 16
#define CIN 512
#define COUT 512
#define HH 64
#define WW 64
#define NPIX (HH*WW)

#define MOD_SCALE 0.04419417382415922f   /* 1/sqrt(512) */
#define CONV_SCALE 0.014731391274719739f /* 1/sqrt(512*9) */

// ---------------- device scratch ----------------
__device__ __half g_Xs[BB * HH * WW * CIN];      // NHWC, x*s in fp16 (67MB)
__device__ __half g_Wh[9 * COUT * CIN];          // [tap][co][ci] fp16 (4.7MB)
__device__ float  g_W2[COUT * CIN];              // sum over taps of w^2
__device__ float  g_s[BB * CIN];                 // modulation
__device__ float  g_alpha[BB * COUT];            // demod * CONV_SCALE

// ---------------- kernel 1: s[b,ci] = style @ (mod_weight*MOD_SCALE)^T + bias ----------------
__global__ void mod_kernel(const float* __restrict__ style,
                           const float* __restrict__ mw,
                           const float* __restrict__ bias) {
    int warp = (blockIdx.x * blockDim.x + threadIdx.x) >> 5;
    int lane = threadIdx.x & 31;
    if (warp >= BB * CIN) return;
    int b = warp >> 9, ci = warp & 511;
    float sum = 0.f;
    const float* st = style + b * 512;
    const float* w  = mw + ci * 512;
    for (int d = lane; d < 512; d += 32) sum += st[d] * w[d];
    #pragma unroll
    for (int off = 16; off > 0; off >>= 1) sum += __shfl_xor_sync(0xffffffffu, sum, off);
    if (lane == 0) g_s[b * 512 + ci] = sum * MOD_SCALE + bias[ci];
}

// ---------------- kernel 2: repack weights to fp16 [tap][co][ci]; W2 = sum taps w^2 ----------------
__global__ void prep_kernel(const float* __restrict__ weight) {
    int idx = blockIdx.x * blockDim.x + threadIdx.x;  // co*512+ci
    if (idx >= COUT * CIN) return;
    const float* w = weight + (size_t)idx * 9;
    float s2 = 0.f;
    #pragma unroll
    for (int k = 0; k < 9; k++) {
        float v = w[k];
        s2 += v * v;
        g_Wh[k * (COUT * CIN) + idx] = __float2half(v);
    }
    g_W2[idx] = s2;
}

// ---------------- kernel 3: alpha[b,co] ----------------
__global__ void demod_kernel() {
    int warp = (blockIdx.x * blockDim.x + threadIdx.x) >> 5;
    int lane = threadIdx.x & 31;
    if (warp >= BB * COUT) return;
    int b = warp >> 9, co = warp & 511;
    float sum = 0.f;
    const float* w2 = g_W2 + co * 512;
    const float* sv = g_s + b * 512;
    for (int ci = lane; ci < 512; ci += 32) {
        float s = sv[ci];
        sum += w2[ci] * s * s;
    }
    #pragma unroll
    for (int off = 16; off > 0; off >>= 1) sum += __shfl_xor_sync(0xffffffffu, sum, off);
    if (lane == 0) {
        float d = CONV_SCALE / sqrtf(CONV_SCALE * CONV_SCALE * sum + 1e-8f);
        g_alpha[b * 512 + co] = d;
    }
}

// ---------------- kernel 4: Xs NHWC fp16 = x * s (transpose CHW->HWC) ----------------
__global__ void xs_kernel(const float* __restrict__ x) {
    __shared__ float sm[32][65];
    int b = blockIdx.z, y = blockIdx.y, ci0 = blockIdx.x * 32;
    int tid = threadIdx.x;
    for (int t = tid; t < 2048; t += 256) {
        int i = t >> 6, xc = t & 63;
        sm[i][xc] = x[(((size_t)(b * 512 + ci0 + i) * 64 + y) * 64) + xc];
    }
    __syncthreads();
    for (int t = tid; t < 2048; t += 256) {
        int xc = t >> 5, i = t & 31;
        float s = g_s[b * 512 + ci0 + i];
        g_Xs[((size_t)((b * 64 + y) * 64 + xc) * 512) + ci0 + i] = __float2half(sm[i][xc] * s);
    }
}

// ---------------- kernel 5: implicit-GEMM conv with mma.sync fp16 ----------------
// CTA tile: 128 co x 128 pixels (2 image rows), K-loop over ci chunks of 32 x 9 taps.
// smem: X tile [4 rows][66 cols][40 ci-pad] halfs, W tile [9][128][40] halfs.

#define XS_IDX(r, c, ci) (((r) * 66 + (c)) * 40 + (ci))
#define WS_IDX(t, co, ci) (((t) * 128 + (co)) * 40 + (ci))
#define XS_HALFS (4 * 66 * 40)
#define WS_HALFS (9 * 128 * 40)
#define SMEM_BYTES ((XS_HALFS + WS_HALFS) * 2)

__device__ __forceinline__ void mma_f16(float acc[4], const uint32_t a[4], const uint32_t b2[2]) {
    asm volatile(
        "mma.sync.aligned.m16n8k16.row.col.f32.f16.f16.f32 "
        "{%0,%1,%2,%3}, {%4,%5,%6,%7}, {%8,%9}, {%0,%1,%2,%3};\n"
        : "+f"(acc[0]), "+f"(acc[1]), "+f"(acc[2]), "+f"(acc[3])
        : "r"(a[0]), "r"(a[1]), "r"(a[2]), "r"(a[3]), "r"(b2[0]), "r"(b2[1]));
}

__global__ void __launch_bounds__(256, 2) conv_kernel(float* __restrict__ out) {
    extern __shared__ __half sh[];
    __half* xs = sh;
    __half* ws = sh + XS_HALFS;

    const int tid  = threadIdx.x;
    const int lane = tid & 31, warp = tid >> 5;
    const int wm = warp & 3, wn = warp >> 2;           // 4 m-warps x 2 n-warps
    const int g = lane >> 2, tg = lane & 3;
    const int b = blockIdx.z;
    const int co_base = blockIdx.y * 128;
    const int r0 = blockIdx.x * 2;                     // first output row

    float acc[2][8][4];
    #pragma unroll
    for (int mf = 0; mf < 2; mf++)
        #pragma unroll
        for (int nf = 0; nf < 8; nf++)
            #pragma unroll
            for (int i = 0; i < 4; i++) acc[mf][nf][i] = 0.f;

    for (int kc = 0; kc < CIN; kc += 32) {
        __syncthreads();
        // ---- fill X tile: 264 (r,c) slots x 32 ci halfs (4 x uint4 each) ----
        for (int idx = tid; idx < 264 * 4; idx += 256) {
            int v = idx & 3, pair = idx >> 2;
            int r = pair / 66, c = pair - r * 66;
            int iy = r0 - 1 + r, ix = c - 1;
            uint4 val = make_uint4(0u, 0u, 0u, 0u);
            if (iy >= 0 && iy < 64 && ix >= 0 && ix < 64)
                val = *reinterpret_cast<const uint4*>(
                    g_Xs + ((size_t)((b * 64 + iy) * 64 + ix) * 512 + kc + v * 8));
            *reinterpret_cast<uint4*>(xs + XS_IDX(r, c, v * 8)) = val;
        }
        // ---- fill W tile: 9 taps x 128 co x 32 ci ----
        for (int idx = tid; idx < 9 * 128 * 4; idx += 256) {
            int v = idx & 3, co_l = (idx >> 2) & 127, tap = idx >> 9;
            uint4 val = *reinterpret_cast<const uint4*>(
                g_Wh + ((size_t)(tap * 512 + co_base + co_l) * 512 + kc + v * 8));
            *reinterpret_cast<uint4*>(ws + WS_IDX(tap, co_l, v * 8)) = val;
        }
        __syncthreads();

        #pragma unroll
        for (int tap = 0; tap < 9; tap++) {
            const int ky = tap / 3, kx = tap - ky * 3;
            uint32_t A[2][2][4];
            #pragma unroll
            for (int mf = 0; mf < 2; mf++) {
                #pragma unroll
                for (int kf = 0; kf < 2; kf++) {
                    int cos = wm * 32 + mf * 16;
                    int ci0 = kf * 16 + tg * 2;
                    const __half* base = ws + WS_IDX(tap, cos, 0);
                    A[mf][kf][0] = *reinterpret_cast<const uint32_t*>(base + g * 40 + ci0);
                    A[mf][kf][1] = *reinterpret_cast<const uint32_t*>(base + (g + 8) * 40 + ci0);
                    A[mf][kf][2] = *reinterpret_cast<const uint32_t*>(base + g * 40 + ci0 + 8);
                    A[mf][kf][3] = *reinterpret_cast<const uint32_t*>(base + (g + 8) * 40 + ci0 + 8);
                }
            }
            #pragma unroll
            for (int nf = 0; nf < 8; nf++) {
                int p = wn * 64 + nf * 8 + g;
                int r = (p >> 6) + ky;
                int c = (p & 63) + kx;
                const __half* bb = xs + XS_IDX(r, c, 0);
                uint32_t Bv[2][2];
                #pragma unroll
                for (int kf = 0; kf < 2; kf++) {
                    int ci0 = kf * 16 + tg * 2;
                    Bv[kf][0] = *reinterpret_cast<const uint32_t*>(bb + ci0);
                    Bv[kf][1] = *reinterpret_cast<const uint32_t*>(bb + ci0 + 8);
                }
                #pragma unroll
                for (int mf = 0; mf < 2; mf++)
                    #pragma unroll
                    for (int kf = 0; kf < 2; kf++)
                        mma_f16(acc[mf][nf], A[mf][kf], Bv[kf]);
            }
        }
    }

    // ---- epilogue: out = alpha * acc, NCHW fp32 ----
    #pragma unroll
    for (int mf = 0; mf < 2; mf++) {
        int co = co_base + wm * 32 + mf * 16 + g;
        float a0 = g_alpha[b * 512 + co];
        float a1 = g_alpha[b * 512 + co + 8];
        #pragma unroll
        for (int nf = 0; nf < 8; nf++) {
            int p = wn * 64 + nf * 8 + tg * 2;
            int row = r0 + (p >> 6), col = p & 63;
            float2 v0 = make_float2(a0 * acc[mf][nf][0], a0 * acc[mf][nf][1]);
            float2 v1 = make_float2(a1 * acc[mf][nf][2], a1 * acc[mf][nf][3]);
            *reinterpret_cast<float2*>(out + ((size_t)(b * 512 + co) * 4096 + row * 64 + col)) = v0;
            *reinterpret_cast<float2*>(out + ((size_t)(b * 512 + co + 8) * 4096 + row * 64 + col)) = v1;
        }
    }
}

// ---------------- launch ----------------
extern "C" void kernel_launch(void* const* d_in, const int* in_sizes, int n_in,
                              void* d_out, int out_size) {
    const float* x     = (const float*)d_in[0];
    const float* style = (const float*)d_in[1];
    const float* weight= (const float*)d_in[2];
    const float* mw    = (const float*)d_in[3];
    const float* mbias = (const float*)d_in[4];
    float* out = (float*)d_out;

    (void)in_sizes; (void)n_in; (void)out_size;

    cudaFuncSetAttribute(conv_kernel, cudaFuncAttributeMaxDynamicSharedMemorySize, SMEM_BYTES);

    mod_kernel<<<1024, 256>>>(style, mw, mbias);
    prep_kernel<<<1024, 256>>>(weight);
    demod_kernel<<<1024, 256>>>();
    xs_kernel<<<dim3(16, 64, 16), 256>>>(x);
    conv_kernel<<<dim3(32, 4, 16), 256, SMEM_BYTES>>>(out);
}

// round 3
// speedup vs baseline: 1.3603x; 1.3603x over previous
#include <cuda_runtime.h>
#include <cuda_fp16.h>
#include <cstdint>

#define MOD_SCALE 0.04419417382415922f   /* 1/sqrt(512) */
#define CONV_SCALE 0.014731391274719739f /* 1/sqrt(512*9) */

// ---------------- device scratch ----------------
__device__ __align__(16) __half g_Xs[16 * 64 * 64 * 512]; // NHWC x*s fp16
__device__ __align__(16) __half g_Wh[9 * 512 * 512];      // [tap][co][ci] fp16
__device__ float  g_W2[512 * 512];
__device__ float  g_s[16 * 512];
__device__ float  g_alpha[16 * 512];

// ---------------- kernel 1: modulation s ----------------
__global__ void mod_kernel(const float* __restrict__ style,
                           const float* __restrict__ mw,
                           const float* __restrict__ bias) {
    int warp = (blockIdx.x * blockDim.x + threadIdx.x) >> 5;
    int lane = threadIdx.x & 31;
    if (warp >= 16 * 512) return;
    int b = warp >> 9, ci = warp & 511;
    float sum = 0.f;
    const float* st = style + b * 512;
    const float* w  = mw + ci * 512;
    for (int d = lane; d < 512; d += 32) sum += st[d] * w[d];
    #pragma unroll
    for (int off = 16; off > 0; off >>= 1) sum += __shfl_xor_sync(0xffffffffu, sum, off);
    if (lane == 0) g_s[b * 512 + ci] = sum * MOD_SCALE + bias[ci];
}

// ---------------- kernel 2: weights -> fp16 [tap][co][ci]; W2 ----------------
__global__ void prep_kernel(const float* __restrict__ weight) {
    int idx = blockIdx.x * blockDim.x + threadIdx.x;  // co*512+ci
    if (idx >= 512 * 512) return;
    const float* w = weight + (size_t)idx * 9;
    float s2 = 0.f;
    #pragma unroll
    for (int k = 0; k < 9; k++) {
        float v = w[k];
        s2 += v * v;
        g_Wh[k * (512 * 512) + idx] = __float2half(v);
    }
    g_W2[idx] = s2;
}

// ---------------- kernel 3: alpha ----------------
__global__ void demod_kernel() {
    int warp = (blockIdx.x * blockDim.x + threadIdx.x) >> 5;
    int lane = threadIdx.x & 31;
    if (warp >= 16 * 512) return;
    int b = warp >> 9, co = warp & 511;
    float sum = 0.f;
    const float* w2 = g_W2 + co * 512;
    const float* sv = g_s + b * 512;
    for (int ci = lane; ci < 512; ci += 32) {
        float s = sv[ci];
        sum += w2[ci] * s * s;
    }
    #pragma unroll
    for (int off = 16; off > 0; off >>= 1) sum += __shfl_xor_sync(0xffffffffu, sum, off);
    if (lane == 0)
        g_alpha[b * 512 + co] = CONV_SCALE / sqrtf(CONV_SCALE * CONV_SCALE * sum + 1e-8f);
}

// ---------------- kernel 4: Xs NHWC fp16 = x * s (vectorized) ----------------
__global__ void xs_kernel(const float* __restrict__ x) {
    __shared__ float sm[32][65];
    __shared__ float ss[32];
    int b = blockIdx.z, y = blockIdx.y, ci0 = blockIdx.x * 32;
    int tid = threadIdx.x;
    if (tid < 32) ss[tid] = g_s[b * 512 + ci0 + tid];
    {
        int i = tid >> 3;   // ci local 0..31
        int v = tid & 7;    // 2 float4 each
        const float4* src = reinterpret_cast<const float4*>(
            x + (((size_t)(b * 512 + ci0 + i) * 64 + y) * 64));
        float4 f0 = src[v * 2], f1 = src[v * 2 + 1];
        int c = v * 8;
        sm[i][c+0]=f0.x; sm[i][c+1]=f0.y; sm[i][c+2]=f0.z; sm[i][c+3]=f0.w;
        sm[i][c+4]=f1.x; sm[i][c+5]=f1.y; sm[i][c+6]=f1.z; sm[i][c+7]=f1.w;
    }
    __syncthreads();
    {
        int xc = tid >> 2, g = tid & 3;  // col, ci-octet
        union { __half h[8]; uint4 u; } pk;
        #pragma unroll
        for (int j = 0; j < 8; j++)
            pk.h[j] = __float2half(sm[g * 8 + j][xc] * ss[g * 8 + j]);
        *reinterpret_cast<uint4*>(
            g_Xs + ((size_t)((b * 64 + y) * 64 + xc) * 512) + ci0 + g * 8) = pk.u;
    }
}

// ================= conv kernel: mma.sync + ldmatrix + cp.async =================
// CTA: 64 co x 512 px (8 rows). 8 warps = 2 m-warps x 4 n-warps.
// K loop: 16 stages of 32 ci; all 9 taps from resident X tile (10x66 px halo).
// smem (halfs, ci padded to 40): X buf 660*40, W buf 576*40 (9 taps x 64 co), x2 each.

#define XB_HALFS (660 * 40)   /* 26400 -> 52800 B */
#define WB_HALFS (576 * 40)   /* 23040 -> 46080 B */
#define XB_BYTES (XB_HALFS * 2)
#define WB_BYTES (WB_HALFS * 2)
#define SMEM_BYTES (2 * XB_BYTES + 2 * WB_BYTES)   /* 197760 */

__device__ __forceinline__ void cp16(uint32_t dst, const void* src, int sz) {
    asm volatile("cp.async.cg.shared.global [%0], [%1], 16, %2;"
                 :: "r"(dst), "l"(src), "r"(sz) : "memory");
}
__device__ __forceinline__ void cp_commit() {
    asm volatile("cp.async.commit_group;" ::: "memory");
}
__device__ __forceinline__ void ldsm4(uint32_t r[4], uint32_t addr) {
    asm volatile("ldmatrix.sync.aligned.m8n8.x4.shared.b16 {%0,%1,%2,%3}, [%4];"
                 : "=r"(r[0]), "=r"(r[1]), "=r"(r[2]), "=r"(r[3]) : "r"(addr));
}
__device__ __forceinline__ void mma_f16(float acc[4], const uint32_t a[4], const uint32_t b2[2]) {
    asm volatile(
        "mma.sync.aligned.m16n8k16.row.col.f32.f16.f16.f32 "
        "{%0,%1,%2,%3}, {%4,%5,%6,%7}, {%8,%9}, {%0,%1,%2,%3};\n"
        : "+f"(acc[0]), "+f"(acc[1]), "+f"(acc[2]), "+f"(acc[3])
        : "r"(a[0]), "r"(a[1]), "r"(a[2]), "r"(a[3]), "r"(b2[0]), "r"(b2[1]));
}

__device__ __forceinline__ void fill_stage(uint32_t xb, uint32_t wb,
                                           int b, int y0, int co0, int kc, int tid) {
    // X tile: 660 pixels (10 rows x 66 cols incl. halo) x 32 ci (4 x 16B)
    #pragma unroll
    for (int it = 0; it < 11; it++) {
        int i = tid + it * 256;
        if (i < 2640) {
            int v = i & 3, p = i >> 2;
            int r = p / 66, c = p - r * 66;
            int iy = y0 - 1 + r, ix = c - 1;
            int ok = (iy >= 0 && iy < 64 && ix >= 0 && ix < 64) ? 16 : 0;
            int iyc = iy < 0 ? 0 : (iy > 63 ? 63 : iy);
            int ixc = ix < 0 ? 0 : (ix > 63 ? 63 : ix);
            const __half* src = g_Xs + ((size_t)((b * 64 + iyc) * 64 + ixc) * 512 + kc * 32 + v * 8);
            cp16(xb + (uint32_t)(p * 40 + v * 8) * 2, src, ok);
        }
    }
    // W tile: 9 taps x 64 co x 32 ci
    #pragma unroll
    for (int it = 0; it < 9; it++) {
        int i = tid + it * 256;     // 2304 total, exact
        int v = i & 3, row = i >> 2;             // row = tap*64 + co_l
        int tap = row >> 6, co_l = row & 63;
        const __half* src = g_Wh + ((size_t)(tap * 512 + co0 + co_l) * 512 + kc * 32 + v * 8);
        cp16(wb + (uint32_t)(row * 40 + v * 8) * 2, src, 16);
    }
    cp_commit();
}

__global__ void __launch_bounds__(256, 1) conv_kernel(float* __restrict__ out) {
    extern __shared__ __align__(16) __half sh[];
    const uint32_t sbase = (uint32_t)__cvta_generic_to_shared(sh);
    const uint32_t xoff[2] = { sbase, sbase + XB_BYTES };
    const uint32_t woff[2] = { sbase + 2 * XB_BYTES, sbase + 2 * XB_BYTES + WB_BYTES };

    const int tid = threadIdx.x, lane = tid & 31, warp = tid >> 5;
    const int wm = warp & 1, wn = warp >> 1;
    const int b = blockIdx.z, co0 = blockIdx.y * 64, y0 = blockIdx.x * 8;

    // ldmatrix lane address patterns (byte offsets within buffers)
    // A (W): groups 0-7:m0-7/k0  8-15:m8-15/k0  16-23:m0-7/k8  24-31:m8-15/k8
    const int aRow = wm * 32 + ((lane >> 3) & 1) * 8 + (lane & 7);
    const int aK   = (lane >> 4) * 8;
    uint32_t aBase[2];
    #pragma unroll
    for (int mf = 0; mf < 2; mf++)
        aBase[mf] = (uint32_t)(((aRow + mf * 16) * 40 + aK) * 2);
    // B (X): groups 0-7:n0-7/k0  8-15:n0-7/k8  16-23:n8-15/k0  24-31:n8-15/k8
    const int nloc = ((lane >> 4) & 1) * 8 + (lane & 7);
    const int bK   = ((lane >> 3) & 1) * 8;
    uint32_t bBase[8];
    #pragma unroll
    for (int nfp = 0; nfp < 8; nfp++) {
        int px = wn * 128 + nfp * 16 + nloc;
        bBase[nfp] = (uint32_t)((((px >> 6) * 66 + (px & 63)) * 40 + bK) * 2);
    }

    float acc[2][16][4];
    #pragma unroll
    for (int mf = 0; mf < 2; mf++)
        #pragma unroll
        for (int nf = 0; nf < 16; nf++)
            #pragma unroll
            for (int i = 0; i < 4; i++) acc[mf][nf][i] = 0.f;

    // prologue: prefetch stages 0,1
    fill_stage(xoff[0], woff[0], b, y0, co0, 0, tid);
    fill_stage(xoff[1], woff[1], b, y0, co0, 1, tid);

    for (int s = 0; s < 16; s++) {
        if (s < 15) asm volatile("cp.async.wait_group 1;" ::: "memory");
        else        asm volatile("cp.async.wait_group 0;" ::: "memory");
        __syncthreads();

        const uint32_t xB = xoff[s & 1], wB = woff[s & 1];
        #pragma unroll
        for (int tap = 0; tap < 9; tap++) {
            const int ky = tap / 3, kx = tap - ky * 3;
            const uint32_t tofsB = (uint32_t)((ky * 66 + kx) * 80);
            const uint32_t tofsA = (uint32_t)(tap * 5120);
            #pragma unroll
            for (int ks = 0; ks < 2; ks++) {
                uint32_t a0[4], a1[4];
                ldsm4(a0, wB + aBase[0] + tofsA + ks * 32);
                ldsm4(a1, wB + aBase[1] + tofsA + ks * 32);
                #pragma unroll
                for (int nfp = 0; nfp < 8; nfp++) {
                    uint32_t bb[4];
                    ldsm4(bb, xB + bBase[nfp] + tofsB + ks * 32);
                    mma_f16(acc[0][2 * nfp],     a0, bb);
                    mma_f16(acc[0][2 * nfp + 1], a0, bb + 2);
                    mma_f16(acc[1][2 * nfp],     a1, bb);
                    mma_f16(acc[1][2 * nfp + 1], a1, bb + 2);
                }
            }
        }
        __syncthreads();
        if (s + 2 < 16) fill_stage(xoff[s & 1], woff[s & 1], b, y0, co0, s + 2, tid);
    }

    // ---- epilogue: out = alpha * acc, NCHW fp32 ----
    #pragma unroll
    for (int mf = 0; mf < 2; mf++) {
        int cobase = co0 + wm * 32 + mf * 16 + (lane >> 2);
        float al0 = g_alpha[b * 512 + cobase];
        float al1 = g_alpha[b * 512 + cobase + 8];
        float* o0 = out + ((size_t)(b * 512 + cobase)) * 4096;
        float* o1 = o0 + 8 * 4096;
        #pragma unroll
        for (int nf = 0; nf < 16; nf++) {
            int px = wn * 128 + nf * 8 + (lane & 3) * 2;
            int ofs = (y0 + (px >> 6)) * 64 + (px & 63);
            *reinterpret_cast<float2*>(o0 + ofs) =
                make_float2(al0 * acc[mf][nf][0], al0 * acc[mf][nf][1]);
            *reinterpret_cast<float2*>(o1 + ofs) =
                make_float2(al1 * acc[mf][nf][2], al1 * acc[mf][nf][3]);
        }
    }
}

// ---------------- launch ----------------
extern "C" void kernel_launch(void* const* d_in, const int* in_sizes, int n_in,
                              void* d_out, int out_size) {
    const float* x     = (const float*)d_in[0];
    const float* style = (const float*)d_in[1];
    const float* weight= (const float*)d_in[2];
    const float* mw    = (const float*)d_in[3];
    const float* mbias = (const float*)d_in[4];
    float* out = (float*)d_out;
    (void)in_sizes; (void)n_in; (void)out_size;

    cudaFuncSetAttribute(conv_kernel, cudaFuncAttributeMaxDynamicSharedMemorySize, SMEM_BYTES);

    mod_kernel<<<1024, 256>>>(style, mw, mbias);
    prep_kernel<<<1024, 256>>>(weight);
    demod_kernel<<<1024, 256>>>();
    xs_kernel<<<dim3(16, 64, 16), 256>>>(x);
    conv_kernel<<<dim3(8, 8, 16), 256, SMEM_BYTES>>>(out);
}